// round 1
// baseline (speedup 1.0000x reference)
#include <cuda_runtime.h>

#define NPTS 1024

// ---------------- packed f32x2 helpers (Blackwell FFMA2) ----------------
static __device__ __forceinline__ unsigned long long pack2(float lo, float hi) {
    unsigned long long r;
    asm("mov.b64 %0, {%1,%2};" : "=l"(r) : "f"(lo), "f"(hi));
    return r;
}
static __device__ __forceinline__ float2 unpack2(unsigned long long v) {
    float2 r;
    asm("mov.b64 {%0,%1}, %2;" : "=f"(r.x), "=f"(r.y) : "l"(v));
    return r;
}
static __device__ __forceinline__ void fma2(unsigned long long& d,
                                            unsigned long long a,
                                            unsigned long long b) {
    asm("fma.rn.f32x2 %0, %1, %2, %0;" : "+l"(d) : "l"(a), "l"(b));
}

// pooled[i][o] intermediate (scratch via device global — no allocations allowed)
__device__ float g_pooled[NPTS * 128];

// ============================================================================
// Kernel A: sparse per-pair MLP (5 -> 64 -> 128) + masked max-pool.
// Only pairs with dx^2+dy^2 < 0.25 contribute (relu >= 0, mask in {0,1}).
// 2 rows per block, 128 threads. Thread t owns conv2 output channel t with
// its 64 weights duplicated into f32x2 register pairs; neighbors processed
// 4 at a time so h1 for 4 neighbors loads as one LDS.128.
// ============================================================================
__global__ __launch_bounds__(128, 3) void pool_kernel(
    const float* __restrict__ s,
    const float* __restrict__ w1g, const float* __restrict__ b1g,
    const float* __restrict__ w2g, const float* __restrict__ b2g)
{
    // One 34KB shared pool, reused in two phases:
    //   phase 0: w2 staging with pitch 65 (conflict-free reg copy)
    //   phase 1: s (4096 f) | nbr (1024 int) | h1v (256 f) | w1 (320 f) | b1 (64 f)
    __shared__ __align__(16) float smem[8520];
    __shared__ int cnt, cntp;

    const int tid = threadIdx.x;

    // ---- phase 0: stage conv2_w [128][64] into pitch-65 shared ----
    for (int idx = tid; idx < 128 * 64; idx += 128) {
        int o = idx >> 6, k = idx & 63;
        smem[o * 65 + k] = w2g[idx];
    }
    __syncthreads();

    // per-thread conv2 weights, duplicated for f32x2
    unsigned long long w2d[64];
    {
        const float* row = &smem[tid * 65];   // stride 65: conflict-free
#pragma unroll
        for (int k = 0; k < 64; k++) {
            float w = row[k];
            w2d[k] = pack2(w, w);
        }
    }
    const float b2 = b2g[tid];
    const unsigned long long b2d = pack2(b2, b2);
    __syncthreads();

    // ---- phase 1 layout ----
    float4* s4        = reinterpret_cast<float4*>(smem);            // [1024]
    int*    nbr       = reinterpret_cast<int*>(smem + 4096);        // [1024]
    float4* h1v       = reinterpret_cast<float4*>(smem + 5120);     // [64]
    float*  w1s       = smem + 5376;                                // [320]
    float*  b1s       = smem + 5696;                                // [64]

    for (int j = tid; j < NPTS; j += 128)
        s4[j] = reinterpret_cast<const float4*>(s)[j];
    for (int idx = tid; idx < 64 * 5; idx += 128) w1s[idx] = w1g[idx];
    if (tid < 64) b1s[tid] = b1g[tid];
    __syncthreads();

    const int o2    = tid & 63;   // conv1 channel this thread computes
    const int which = tid >> 6;   // neighbor-slot group {0,2} or {1,3}
    const float w1r0 = w1s[o2 * 5 + 0], w1r1 = w1s[o2 * 5 + 1],
                w1r2 = w1s[o2 * 5 + 2], w1r3 = w1s[o2 * 5 + 3],
                w1r4 = w1s[o2 * 5 + 4], b1r = b1s[o2];

    for (int rr = 0; rr < 2; rr++) {
        const int i = blockIdx.x * 2 + rr;
        if (tid == 0) cnt = 0;
        __syncthreads();

        const float4 si = s4[i];

        // neighbor scan: dx^2+dy^2 < 0.25  (== dist < 0.5; self always passes)
        for (int j = tid; j < NPTS; j += 128) {
            float4 sj = s4[j];
            float dx = si.x - sj.x, dy = si.y - sj.y;
            if (dx * dx + dy * dy < 0.25f) {
                int p = atomicAdd(&cnt, 1);
                nbr[p] = j;
            }
        }
        __syncthreads();
        if (tid == 0) {
            int c = cnt, cp = (c + 3) & ~3;
            for (int t = c; t < cp; t++) nbr[t] = i;  // pad with self: idempotent under max
            cntp = cp;
        }
        __syncthreads();
        const int cp = cntp;

        float pooled = 0.0f;  // max includes 0 (covers mask zeros & relu)

        for (int n = 0; n < cp; n += 4) {
            // conv1: thread computes h1[o2] for slots {which, which+2}
#pragma unroll
            for (int t = 0; t < 2; t++) {
                int sl = which + 2 * t;
                int j  = nbr[n + sl];
                float4 sj = s4[j];
                float dx = si.x - sj.x, dy = si.y - sj.y;
                float dz = si.z - sj.z, dw = si.w - sj.w;
                float ind = (j == i) ? 1.0f : 0.0f;
                float v = b1r;
                v = fmaf(dx, w1r0, v);
                v = fmaf(dy, w1r1, v);
                v = fmaf(dz, w1r2, v);
                v = fmaf(dw, w1r3, v);
                v = fmaf(ind, w1r4, v);
                v = fmaxf(v, 0.0f);
                reinterpret_cast<float*>(&h1v[o2])[sl] = v;
            }
            __syncthreads();

            // conv2: 4 neighbors at once; h1v[k] = {h_n0,h_n1,h_n2,h_n3}[k]
            unsigned long long a01 = b2d, a23 = b2d;
            const ulonglong2* hv = reinterpret_cast<const ulonglong2*>(h1v);
#pragma unroll
            for (int k = 0; k < 64; k++) {
                ulonglong2 hp = hv[k];        // LDS.128, uniform broadcast
                fma2(a01, hp.x, w2d[k]);
                fma2(a23, hp.y, w2d[k]);
            }
            float2 f01 = unpack2(a01), f23 = unpack2(a23);
            pooled = fmaxf(pooled,
                     fmaxf(fmaxf(f01.x, f01.y), fmaxf(f23.x, f23.y)));
            __syncthreads();  // h1v reuse
        }

        g_pooled[i * 128 + tid] = pooled;
    }
}

// ============================================================================
// Kernel B: trunk  feat[132] -> 64 -> 128 -> 64 -> 4 -> (a_x, a_y)
// 128 blocks x 256 threads; warp w handles row r = blockIdx*8 + w.
// Per-layer weights transposed into shared (lane-stride-1 reads).
// ============================================================================
__global__ __launch_bounds__(256) void trunk_kernel(
    const float* __restrict__ s, const float* __restrict__ g,
    const float* __restrict__ fc1w, const float* __restrict__ fc1b,
    const float* __restrict__ fc2w, const float* __restrict__ fc2b,
    const float* __restrict__ fc3w, const float* __restrict__ fc3b,
    const float* __restrict__ fc4w, const float* __restrict__ fc4b,
    float* __restrict__ out)
{
    __shared__ float wT[132 * 64];   // max layer: 8448 floats
    __shared__ float bb[128];
    __shared__ float act[8][132];

    const int tid  = threadIdx.x;
    const int lane = tid & 31;
    const int w    = tid >> 5;
    const int r    = blockIdx.x * 8 + w;

    const float4 sv = reinterpret_cast<const float4*>(s)[r];
    const float2 gv = reinterpret_cast<const float2*>(g)[r];

    // feat = [pooled(128), s0-g0, s1-g1, s2, s3]
    for (int k = lane; k < 132; k += 32) {
        float v;
        if (k < 128)       v = g_pooled[r * 128 + k];
        else if (k == 128) v = sv.x - gv.x;
        else if (k == 129) v = sv.y - gv.y;
        else if (k == 130) v = sv.z;
        else               v = sv.w;
        act[w][k] = v;
    }

    // ---- load fc1 (transposed) ----
    for (int idx = tid; idx < 132 * 64; idx += 256) {
        int o = idx / 132, k = idx - o * 132;
        wT[k * 64 + o] = fc1w[idx];
    }
    if (tid < 64) bb[tid] = fc1b[tid];
    __syncthreads();

    // L1: 132 -> 64
    {
        float a0 = bb[lane], a1 = bb[lane + 32];
#pragma unroll 4
        for (int k = 0; k < 132; k++) {
            float a = act[w][k];
            a0 = fmaf(a, wT[k * 64 + lane], a0);
            a1 = fmaf(a, wT[k * 64 + lane + 32], a1);
        }
        a0 = fmaxf(a0, 0.0f); a1 = fmaxf(a1, 0.0f);
        __syncthreads();                  // all warps done with fc1 weights
        act[w][lane] = a0; act[w][lane + 32] = a1;
    }

    // ---- load fc2 ----
    for (int idx = tid; idx < 64 * 128; idx += 256) {
        int o = idx >> 6, k = idx & 63;
        wT[k * 128 + o] = fc2w[idx];
    }
    if (tid < 128) bb[tid] = fc2b[tid];
    __syncthreads();

    // L2: 64 -> 128
    {
        float a0 = bb[lane], a1 = bb[lane + 32], a2 = bb[lane + 64], a3 = bb[lane + 96];
#pragma unroll 4
        for (int k = 0; k < 64; k++) {
            float a = act[w][k];
            a0 = fmaf(a, wT[k * 128 + lane],      a0);
            a1 = fmaf(a, wT[k * 128 + lane + 32], a1);
            a2 = fmaf(a, wT[k * 128 + lane + 64], a2);
            a3 = fmaf(a, wT[k * 128 + lane + 96], a3);
        }
        a0 = fmaxf(a0, 0.0f); a1 = fmaxf(a1, 0.0f);
        a2 = fmaxf(a2, 0.0f); a3 = fmaxf(a3, 0.0f);
        __syncthreads();
        act[w][lane] = a0; act[w][lane + 32] = a1;
        act[w][lane + 64] = a2; act[w][lane + 96] = a3;
    }

    // ---- load fc3 ----
    for (int idx = tid; idx < 128 * 64; idx += 256) {
        int o = idx >> 7, k = idx & 127;
        wT[k * 64 + o] = fc3w[idx];
    }
    if (tid < 64) bb[tid] = fc3b[tid];
    __syncthreads();

    // L3: 128 -> 64
    {
        float a0 = bb[lane], a1 = bb[lane + 32];
#pragma unroll 4
        for (int k = 0; k < 128; k++) {
            float a = act[w][k];
            a0 = fmaf(a, wT[k * 64 + lane], a0);
            a1 = fmaf(a, wT[k * 64 + lane + 32], a1);
        }
        a0 = fmaxf(a0, 0.0f); a1 = fmaxf(a1, 0.0f);
        __syncthreads();
        act[w][lane] = a0; act[w][lane + 32] = a1;
    }

    // ---- load fc4 ----
    for (int idx = tid; idx < 64 * 4; idx += 256) {
        int o = idx >> 6, k = idx & 63;
        wT[k * 4 + o] = fc4w[idx];
    }
    if (tid < 4) bb[tid] = fc4b[tid];
    __syncthreads();

    // L4: 64 -> 4, sigmoid, gains
    {
        int ol = lane & 3;
        float acc = bb[ol];
#pragma unroll 4
        for (int k = 0; k < 64; k++)
            acc = fmaf(act[w][k], wT[k * 4 + ol], acc);
        float kv = 2.0f / (1.0f + expf(-acc)) - 1.0f;

        float k1 = __shfl_sync(0xffffffffu, kv, 0);
        float k2 = __shfl_sync(0xffffffffu, kv, 1);
        float k3 = __shfl_sync(0xffffffffu, kv, 2);
        float k4 = __shfl_sync(0xffffffffu, kv, 3);

        if (lane == 0) {
            float sg0 = sv.x - gv.x;
            float sg1 = sv.y - gv.y;
            float ax = -(k1 * sg0 + k2 * sv.z);
            float ay = -(k3 * sg1 + k4 * sv.w);
            out[r * 2 + 0] = ax;
            out[r * 2 + 1] = ay;
        }
    }
}

// ============================================================================
extern "C" void kernel_launch(void* const* d_in, const int* in_sizes, int n_in,
                              void* d_out, int out_size)
{
    const float* s    = (const float*)d_in[0];
    const float* g    = (const float*)d_in[1];
    const float* c1w  = (const float*)d_in[2];
    const float* c1b  = (const float*)d_in[3];
    const float* c2w  = (const float*)d_in[4];
    const float* c2b  = (const float*)d_in[5];
    const float* f1w  = (const float*)d_in[6];
    const float* f1b  = (const float*)d_in[7];
    const float* f2w  = (const float*)d_in[8];
    const float* f2b  = (const float*)d_in[9];
    const float* f3w  = (const float*)d_in[10];
    const float* f3b  = (const float*)d_in[11];
    const float* f4w  = (const float*)d_in[12];
    const float* f4b  = (const float*)d_in[13];
    float* out = (float*)d_out;

    pool_kernel<<<NPTS / 2, 128>>>(s, c1w, c1b, c2w, c2b);
    trunk_kernel<<<NPTS / 8, 256>>>(s, g, f1w, f1b, f2w, f2b, f3w, f3b,
                                    f4w, f4b, out);
}

// round 3
// speedup vs baseline: 1.1275x; 1.1275x over previous
#include <cuda_runtime.h>

#define NPTS 1024

// ---------------- packed f32x2 helpers (Blackwell) ----------------
static __device__ __forceinline__ unsigned long long pack2(float lo, float hi) {
    unsigned long long r;
    asm("mov.b64 %0, {%1,%2};" : "=l"(r) : "f"(lo), "f"(hi));
    return r;
}
static __device__ __forceinline__ float2 unpack2(unsigned long long v) {
    float2 r;
    asm("mov.b64 {%0,%1}, %2;" : "=f"(r.x), "=f"(r.y) : "l"(v));
    return r;
}
static __device__ __forceinline__ void fma2(unsigned long long& d,
                                            unsigned long long a,
                                            unsigned long long b) {
    asm("fma.rn.f32x2 %0, %1, %2, %0;" : "+l"(d) : "l"(a), "l"(b));
}

// pooled[i][o] intermediate (device-global scratch; no allocations allowed)
__device__ float g_pooled[NPTS * 128];

// ============================================================================
// Kernel A: sparse per-pair MLP (5 -> 64 -> 128) + masked max-pool.
// Only pairs with dx^2+dy^2 < 0.25 contribute (relu >= 0, mask in {0,1}).
// 1 row per block, 128 threads. Thread t owns conv2 channel t with its 64
// weights packed over k-PAIRS into 32 u64 registers; neighbors processed
// 8 at a time, h1 read as LDS.128 broadcasts (4 k = 2 fma2).
// ============================================================================
__global__ __launch_bounds__(128, 4) void pool_kernel(
    const float* __restrict__ s,
    const float* __restrict__ w1g, const float* __restrict__ b1g,
    const float* __restrict__ w2g, const float* __restrict__ b2g)
{
    // One 33.3KB shared pool, reused in two phases:
    //   phase 0: w2 staging, pitch 65 (conflict-free register copy)
    //   phase 1: s (4096 f) | nbr (1024 int) | h1 (512 f) | w1 (320 f) | b1 (64 f)
    __shared__ __align__(16) float smem[128 * 65];
    __shared__ int cnt, cntp;

    const int tid = threadIdx.x;

    // ---- phase 0: stage conv2_w [128][64] into pitch-65 shared ----
    for (int idx = tid; idx < 128 * 64; idx += 128) {
        int o = idx >> 6, k = idx & 63;
        smem[o * 65 + k] = w2g[idx];
    }
    __syncthreads();

    // per-thread conv2 weights as 32 k-pair packs (64 registers)
    unsigned long long w2p[32];
    {
        const float* row = &smem[tid * 65];   // stride 65: conflict-free
#pragma unroll
        for (int q = 0; q < 32; q++)
            w2p[q] = pack2(row[2 * q], row[2 * q + 1]);
    }
    const float b2 = b2g[tid];
    __syncthreads();

    // ---- phase 1 layout ----
    float4* s4  = reinterpret_cast<float4*>(smem);        // [1024] float4
    int*    nbr = reinterpret_cast<int*>(smem + 4096);    // [1024]
    float*  h1  = smem + 5120;                            // [8][64]
    float*  w1s = smem + 5632;                            // [320]
    float*  b1s = smem + 5952;                            // [64]

    for (int j = tid; j < NPTS; j += 128)
        s4[j] = reinterpret_cast<const float4*>(s)[j];
    for (int idx = tid; idx < 64 * 5; idx += 128) w1s[idx] = w1g[idx];
    if (tid < 64) b1s[tid] = b1g[tid];
    if (tid == 0) cnt = 0;
    __syncthreads();

    const int o2  = tid & 63;   // conv1 channel this thread computes
    const int grp = tid >> 6;   // neighbor-slot subgroup {0,1}
    const float w1r0 = w1s[o2 * 5 + 0], w1r1 = w1s[o2 * 5 + 1],
                w1r2 = w1s[o2 * 5 + 2], w1r3 = w1s[o2 * 5 + 3],
                w1r4 = w1s[o2 * 5 + 4], b1r = b1s[o2];

    const int i = blockIdx.x;
    const float4 si = s4[i];

    // neighbor scan: dx^2+dy^2 < 0.25  (== dist < 0.5; self always passes)
    for (int j = tid; j < NPTS; j += 128) {
        float4 sj = s4[j];
        float dx = si.x - sj.x, dy = si.y - sj.y;
        if (dx * dx + dy * dy < 0.25f) {
            int p = atomicAdd(&cnt, 1);
            nbr[p] = j;
        }
    }
    __syncthreads();
    if (tid == 0) {
        int c = cnt, cp = (c + 7) & ~7;
        for (int t = c; t < cp; t++) nbr[t] = i;  // pad with self (idempotent under max)
        cntp = cp;
    }
    __syncthreads();
    const int cp = cntp;

    float pooled = 0.0f;  // max vs 0 covers mask zeros & relu

    for (int n = 0; n < cp; n += 8) {
        // conv1: thread computes h1[o2] for slots {grp, grp+2, grp+4, grp+6}
#pragma unroll
        for (int t = 0; t < 4; t++) {
            int sl = grp + 2 * t;
            int j  = nbr[n + sl];
            float4 sj = s4[j];
            float dx = si.x - sj.x, dy = si.y - sj.y;
            float dz = si.z - sj.z, dw = si.w - sj.w;
            float ind = (j == i) ? 1.0f : 0.0f;
            float v = b1r;
            v = fmaf(dx, w1r0, v);
            v = fmaf(dy, w1r1, v);
            v = fmaf(dz, w1r2, v);
            v = fmaf(dw, w1r3, v);
            v = fmaf(ind, w1r4, v);
            h1[sl * 64 + o2] = fmaxf(v, 0.0f);   // lane-consecutive: conflict-free
        }
        __syncthreads();

        // conv2: 8 neighbors, accumulator per neighbor, k-pairs via f32x2
        unsigned long long acc[8];
#pragma unroll
        for (int nn = 0; nn < 8; nn++) acc[nn] = 0ull;

#pragma unroll
        for (int q = 0; q < 16; q++) {
#pragma unroll
            for (int nn = 0; nn < 8; nn++) {
                // LDS.128 broadcast: h1[nn][4q .. 4q+3]
                ulonglong2 hp = *reinterpret_cast<const ulonglong2*>(h1 + nn * 64 + q * 4);
                fma2(acc[nn], hp.x, w2p[2 * q]);
                fma2(acc[nn], hp.y, w2p[2 * q + 1]);
            }
        }
#pragma unroll
        for (int nn = 0; nn < 8; nn++) {
            float2 f = unpack2(acc[nn]);
            pooled = fmaxf(pooled, f.x + f.y + b2);
        }
        __syncthreads();  // h1 reuse
    }

    g_pooled[i * 128 + tid] = pooled;
}

// ============================================================================
// Kernel B: trunk  feat[132] -> 64 -> 128 -> 64 -> 4 -> (a_x, a_y)
// 256 blocks x 128 threads; warp w handles row r = blockIdx*4 + w.
// Weights transposed into shared with ODD pitch (65/129) so staging stores
// and compute loads are both bank-conflict-free.
// ============================================================================
__global__ __launch_bounds__(128) void trunk_kernel(
    const float* __restrict__ s, const float* __restrict__ g,
    const float* __restrict__ fc1w, const float* __restrict__ fc1b,
    const float* __restrict__ fc2w, const float* __restrict__ fc2b,
    const float* __restrict__ fc3w, const float* __restrict__ fc3b,
    const float* __restrict__ fc4w, const float* __restrict__ fc4b,
    float* __restrict__ out)
{
    __shared__ float wT[132 * 65];   // largest: fc1 transposed, pitch 65
    __shared__ float w4[64 * 4];
    __shared__ float bb[128];
    __shared__ float b4s[4];
    __shared__ float act[4][132];

    const int tid  = threadIdx.x;
    const int lane = tid & 31;
    const int w    = tid >> 5;
    const int r    = blockIdx.x * 4 + w;

    const float4 sv = reinterpret_cast<const float4*>(s)[r];
    const float2 gv = reinterpret_cast<const float2*>(g)[r];

    // feat = [pooled(128), s0-g0, s1-g1, s2, s3]
    for (int k = lane; k < 128; k += 32)
        act[w][k] = g_pooled[r * 128 + k];
    if (lane == 0) {
        act[w][128] = sv.x - gv.x;
        act[w][129] = sv.y - gv.y;
        act[w][130] = sv.z;
        act[w][131] = sv.w;
    }

    // fc4 is tiny: stage it up front (transposed, pitch 4).
    // R2 BUG FIX: strided loop (blockDim=128 < 256 elements).
    for (int idx = tid; idx < 64 * 4; idx += 128) {
        int o = idx >> 6, k = idx & 63;
        w4[k * 4 + o] = fc4w[idx];
    }
    if (tid < 4) b4s[tid] = fc4b[tid];

    // ---- fc1 (transposed, pitch 65: conflict-free stores AND loads) ----
    for (int idx = tid; idx < 64 * 132; idx += 128) {
        int o = idx / 132, k = idx - o * 132;
        wT[k * 65 + o] = fc1w[idx];
    }
    if (tid < 64) bb[tid] = fc1b[tid];
    __syncthreads();

    // L1: 132 -> 64
    {
        float a0 = bb[lane], a1 = bb[lane + 32];
#pragma unroll 4
        for (int k = 0; k < 132; k++) {
            float a = act[w][k];
            a0 = fmaf(a, wT[k * 65 + lane], a0);
            a1 = fmaf(a, wT[k * 65 + lane + 32], a1);
        }
        a0 = fmaxf(a0, 0.0f); a1 = fmaxf(a1, 0.0f);
        __syncthreads();
        act[w][lane] = a0; act[w][lane + 32] = a1;
    }

    // ---- fc2 (pitch 129) ----
    for (int idx = tid; idx < 128 * 64; idx += 128) {
        int o = idx >> 6, k = idx & 63;
        wT[k * 129 + o] = fc2w[idx];
    }
    if (tid < 128) bb[tid] = fc2b[tid];
    __syncthreads();

    // L2: 64 -> 128
    {
        float a0 = bb[lane], a1 = bb[lane + 32], a2 = bb[lane + 64], a3 = bb[lane + 96];
#pragma unroll 4
        for (int k = 0; k < 64; k++) {
            float a = act[w][k];
            a0 = fmaf(a, wT[k * 129 + lane],      a0);
            a1 = fmaf(a, wT[k * 129 + lane + 32], a1);
            a2 = fmaf(a, wT[k * 129 + lane + 64], a2);
            a3 = fmaf(a, wT[k * 129 + lane + 96], a3);
        }
        a0 = fmaxf(a0, 0.0f); a1 = fmaxf(a1, 0.0f);
        a2 = fmaxf(a2, 0.0f); a3 = fmaxf(a3, 0.0f);
        __syncthreads();
        act[w][lane] = a0; act[w][lane + 32] = a1;
        act[w][lane + 64] = a2; act[w][lane + 96] = a3;
    }

    // ---- fc3 (pitch 65) ----
    for (int idx = tid; idx < 64 * 128; idx += 128) {
        int o = idx >> 7, k = idx & 127;
        wT[k * 65 + o] = fc3w[idx];
    }
    if (tid < 64) bb[tid] = fc3b[tid];
    __syncthreads();

    // L3: 128 -> 64
    {
        float a0 = bb[lane], a1 = bb[lane + 32];
#pragma unroll 4
        for (int k = 0; k < 128; k++) {
            float a = act[w][k];
            a0 = fmaf(a, wT[k * 65 + lane], a0);
            a1 = fmaf(a, wT[k * 65 + lane + 32], a1);
        }
        a0 = fmaxf(a0, 0.0f); a1 = fmaxf(a1, 0.0f);
        __syncwarp();
        act[w][lane] = a0; act[w][lane + 32] = a1;
        __syncwarp();
    }

    // L4: 64 -> 4, sigmoid, gains (per-warp, no cross-warp deps)
    {
        int ol = lane & 3;
        float acc = b4s[ol];
#pragma unroll 4
        for (int k = 0; k < 64; k++)
            acc = fmaf(act[w][k], w4[k * 4 + ol], acc);
        float kv = 2.0f / (1.0f + expf(-acc)) - 1.0f;

        float k1 = __shfl_sync(0xffffffffu, kv, 0);
        float k2 = __shfl_sync(0xffffffffu, kv, 1);
        float k3 = __shfl_sync(0xffffffffu, kv, 2);
        float k4 = __shfl_sync(0xffffffffu, kv, 3);

        if (lane == 0) {
            float sg0 = sv.x - gv.x;
            float sg1 = sv.y - gv.y;
            out[r * 2 + 0] = -(k1 * sg0 + k2 * sv.z);
            out[r * 2 + 1] = -(k3 * sg1 + k4 * sv.w);
        }
    }
}

// ============================================================================
extern "C" void kernel_launch(void* const* d_in, const int* in_sizes, int n_in,
                              void* d_out, int out_size)
{
    const float* s    = (const float*)d_in[0];
    const float* g    = (const float*)d_in[1];
    const float* c1w  = (const float*)d_in[2];
    const float* c1b  = (const float*)d_in[3];
    const float* c2w  = (const float*)d_in[4];
    const float* c2b  = (const float*)d_in[5];
    const float* f1w  = (const float*)d_in[6];
    const float* f1b  = (const float*)d_in[7];
    const float* f2w  = (const float*)d_in[8];
    const float* f2b  = (const float*)d_in[9];
    const float* f3w  = (const float*)d_in[10];
    const float* f3b  = (const float*)d_in[11];
    const float* f4w  = (const float*)d_in[12];
    const float* f4b  = (const float*)d_in[13];
    float* out = (float*)d_out;

    pool_kernel<<<NPTS, 128>>>(s, c1w, c1b, c2w, c2b);
    trunk_kernel<<<NPTS / 4, 128>>>(s, g, f1w, f1b, f2w, f2b, f3w, f3b,
                                    f4w, f4b, out);
}

// round 4
// speedup vs baseline: 1.8118x; 1.6070x over previous
#include <cuda_runtime.h>

#define NPTS 1024

// ---------------- packed f32x2 helpers (Blackwell) ----------------
static __device__ __forceinline__ unsigned long long pack2(float lo, float hi) {
    unsigned long long r;
    asm("mov.b64 %0, {%1,%2};" : "=l"(r) : "f"(lo), "f"(hi));
    return r;
}
static __device__ __forceinline__ float2 unpack2(unsigned long long v) {
    float2 r;
    asm("mov.b64 {%0,%1}, %2;" : "=f"(r.x), "=f"(r.y) : "l"(v));
    return r;
}
static __device__ __forceinline__ void fma2(unsigned long long& d,
                                            unsigned long long a,
                                            unsigned long long b) {
    asm("fma.rn.f32x2 %0, %1, %2, %0;" : "+l"(d) : "l"(a), "l"(b));
}

// pooled[i][o] intermediate (device-global scratch; no allocations allowed)
__device__ float g_pooled[NPTS * 128];

// ============================================================================
// Kernel A: sparse per-pair MLP (5 -> 64 -> 128) + masked max-pool.
// Split-k: 256 threads; thread = (ch in 0..127, half in {0,1}).
// Each thread holds 32 of channel ch's conv2 weights as 16 f32x2 packs
// (direct float4 LDG, no smem staging). 8 neighbors per group; halves
// combined through a shared partial buffer.
// ============================================================================
__global__ __launch_bounds__(256, 2) void pool_kernel(
    const float* __restrict__ s,
    const float* __restrict__ w1g, const float* __restrict__ b1g,
    const float* __restrict__ w2g, const float* __restrict__ b2g)
{
    __shared__ __align__(16) float4 s4[NPTS];        // 16KB
    __shared__ int   nbr[NPTS];                      // 4KB
    __shared__ __align__(16) float h1[8 * 64];       // 2KB
    __shared__ float part[2][8][128];                // 8KB
    __shared__ float w1s[64 * 5];
    __shared__ float b1s[64];
    __shared__ int cnt, cntp;

    const int tid  = threadIdx.x;
    const int ch   = tid & 127;       // conv2 output channel
    const int half = tid >> 7;        // k-half: 0 -> k[0:32), 1 -> k[32:64)

    // ---- conv2 weights: 8 independent LDG.128, pack to 16 f32x2 ----
    unsigned long long w2p[16];
    {
        const float4* wrow = reinterpret_cast<const float4*>(w2g + ch * 64 + half * 32);
        float4 wv[8];
#pragma unroll
        for (int q = 0; q < 8; q++) wv[q] = wrow[q];
#pragma unroll
        for (int q = 0; q < 8; q++) {
            w2p[2 * q]     = pack2(wv[q].x, wv[q].y);
            w2p[2 * q + 1] = pack2(wv[q].z, wv[q].w);
        }
    }
    const float b2 = b2g[ch];

    // ---- stage s (4 batched LDG.128 each), w1, b1 ----
#pragma unroll
    for (int j = 0; j < 4; j++)
        s4[tid + 256 * j] = reinterpret_cast<const float4*>(s)[tid + 256 * j];
    for (int idx = tid; idx < 320; idx += 256) w1s[idx] = w1g[idx];
    if (tid < 64) b1s[tid] = b1g[tid];
    if (tid == 0) cnt = 0;
    __syncthreads();

    const int   c1  = tid & 63;   // conv1 channel this thread computes
    const int   slb = tid >> 6;   // base slot 0..3 (handles slb and slb+4)
    const float w1r0 = w1s[c1 * 5 + 0], w1r1 = w1s[c1 * 5 + 1],
                w1r2 = w1s[c1 * 5 + 2], w1r3 = w1s[c1 * 5 + 3],
                w1r4 = w1s[c1 * 5 + 4], b1r = b1s[c1];

    const int i = blockIdx.x;
    const float4 si = s4[i];

    // ---- neighbor scan: dx^2+dy^2 < 0.25 (== dist < 0.5; self passes) ----
    for (int j = tid; j < NPTS; j += 256) {
        float4 sj = s4[j];
        float dx = si.x - sj.x, dy = si.y - sj.y;
        if (dx * dx + dy * dy < 0.25f) {
            int p = atomicAdd(&cnt, 1);
            nbr[p] = j;
        }
    }
    __syncthreads();
    if (tid == 0) {
        int c = cnt, cp = (c + 7) & ~7;
        for (int t = c; t < cp; t++) nbr[t] = i;  // pad with self (idempotent under max)
        cntp = cp;
    }
    __syncthreads();
    const int cp = cntp;

    float pooled = 0.0f;  // max vs 0 covers mask zeros & relu

    for (int n = 0; n < cp; n += 8) {
        // conv1: thread computes h1[c1] for slots slb and slb+4
#pragma unroll
        for (int t = 0; t < 2; t++) {
            int sl = slb + 4 * t;
            int j  = nbr[n + sl];
            float4 sj = s4[j];
            float dx = si.x - sj.x, dy = si.y - sj.y;
            float dz = si.z - sj.z, dw = si.w - sj.w;
            float ind = (j == i) ? 1.0f : 0.0f;
            float v = b1r;
            v = fmaf(dx, w1r0, v);
            v = fmaf(dy, w1r1, v);
            v = fmaf(dz, w1r2, v);
            v = fmaf(dw, w1r3, v);
            v = fmaf(ind, w1r4, v);
            h1[sl * 64 + c1] = fmaxf(v, 0.0f);   // lane-consecutive: conflict-free
        }
        __syncthreads();

        // conv2: 8 neighbors x 32 k's (this half) via f32x2
        unsigned long long acc[8];
#pragma unroll
        for (int nn = 0; nn < 8; nn++) acc[nn] = 0ull;

#pragma unroll
        for (int nn = 0; nn < 8; nn++) {
            const ulonglong2* hb =
                reinterpret_cast<const ulonglong2*>(h1 + nn * 64 + half * 32);
#pragma unroll
            for (int q = 0; q < 8; q++) {
                ulonglong2 hp = hb[q];            // LDS.128 broadcast
                fma2(acc[nn], hp.x, w2p[2 * q]);
                fma2(acc[nn], hp.y, w2p[2 * q + 1]);
            }
        }
#pragma unroll
        for (int nn = 0; nn < 8; nn++) {
            float2 f = unpack2(acc[nn]);
            part[half][nn][ch] = f.x + f.y;       // conflict-free (ch consecutive)
        }
        __syncthreads();

        if (half == 0) {
#pragma unroll
            for (int nn = 0; nn < 8; nn++) {
                float v = part[0][nn][ch] + part[1][nn][ch] + b2;
                pooled = fmaxf(pooled, v);
            }
        }
        // next group's conv1 h1 writes are safe: all h1 reads done before the
        // barrier above; part reads (half 0) complete before next conv1 barrier.
    }

    if (half == 0)
        g_pooled[i * 128 + ch] = pooled;
}

// ============================================================================
// Kernel B: trunk  feat[132] -> 64 -> 128 -> 64 -> 4 -> (a_x, a_y)
// 128 blocks x 256 threads (8 warps), 1 row per warp.
// Staging uses batched float4 loads (the R3 version exposed full L2 latency
// per scalar staging load). Odd pitches keep LDS conflict-free.
// ============================================================================
__global__ __launch_bounds__(256) void trunk_kernel(
    const float* __restrict__ s, const float* __restrict__ g,
    const float* __restrict__ fc1w, const float* __restrict__ fc1b,
    const float* __restrict__ fc2w, const float* __restrict__ fc2b,
    const float* __restrict__ fc3w, const float* __restrict__ fc3b,
    const float* __restrict__ fc4w, const float* __restrict__ fc4b,
    float* __restrict__ out)
{
    __shared__ float wT[132 * 65];   // reused per layer (fc1/fc2/fc3)
    __shared__ float w4[64 * 4];
    __shared__ float bb1[64], bb2[128], bb3[64], b4s[4];
    __shared__ float act[8][132];

    const int tid  = threadIdx.x;
    const int lane = tid & 31;
    const int w    = tid >> 5;
    const int r    = blockIdx.x * 8 + w;

    const float4 sv = reinterpret_cast<const float4*>(s)[r];
    const float2 gv = reinterpret_cast<const float2*>(g)[r];

    // feat = [pooled(128), s0-g0, s1-g1, s2, s3]
#pragma unroll
    for (int j = 0; j < 4; j++)
        act[w][lane + 32 * j] = g_pooled[r * 128 + lane + 32 * j];
    if (lane == 0) {
        act[w][128] = sv.x - gv.x;
        act[w][129] = sv.y - gv.y;
        act[w][130] = sv.z;
        act[w][131] = sv.w;
    }

    // ---- stage all biases + fc4 up front ----
    if (tid < 64)  bb1[tid] = fc1b[tid];
    if (tid < 128) bb2[tid] = fc2b[tid];
    if (tid >= 128 && tid < 192) bb3[tid - 128] = fc3b[tid - 128];
    if (tid < 4)   b4s[tid] = fc4b[tid];
    if (tid < 64) {                       // fc4: 64 float4s
        float4 v = reinterpret_cast<const float4*>(fc4w)[tid];
        int o = tid >> 4;                 // (tid*4)/64
        int k = (tid << 2) & 63;
        w4[(k + 0) * 4 + o] = v.x; w4[(k + 1) * 4 + o] = v.y;
        w4[(k + 2) * 4 + o] = v.z; w4[(k + 3) * 4 + o] = v.w;
    }

    // ---- fc1 staging: [64][132] -> wT[k*65+o], 2112 float4 ----
#pragma unroll 2
    for (int idx4 = tid; idx4 < 2112; idx4 += 256) {
        float4 v = reinterpret_cast<const float4*>(fc1w)[idx4];
        int e = idx4 << 2;
        int o = e / 132;                  // 132 % 4 == 0: no row straddle
        int k = e - o * 132;
        wT[(k + 0) * 65 + o] = v.x; wT[(k + 1) * 65 + o] = v.y;
        wT[(k + 2) * 65 + o] = v.z; wT[(k + 3) * 65 + o] = v.w;
    }
    __syncthreads();

    // L1: 132 -> 64
    {
        float a0 = bb1[lane], a1 = bb1[lane + 32];
#pragma unroll 4
        for (int k = 0; k < 132; k++) {
            float a = act[w][k];
            a0 = fmaf(a, wT[k * 65 + lane], a0);
            a1 = fmaf(a, wT[k * 65 + lane + 32], a1);
        }
        a0 = fmaxf(a0, 0.0f); a1 = fmaxf(a1, 0.0f);
        __syncthreads();                  // all warps done with fc1 weights
        act[w][lane] = a0; act[w][lane + 32] = a1;
    }

    // ---- fc2 staging: [128][64] -> wT[k*129+o], 2048 float4 ----
#pragma unroll 2
    for (int idx4 = tid; idx4 < 2048; idx4 += 256) {
        float4 v = reinterpret_cast<const float4*>(fc2w)[idx4];
        int e = idx4 << 2;
        int o = e >> 6;
        int k = e & 63;
        wT[(k + 0) * 129 + o] = v.x; wT[(k + 1) * 129 + o] = v.y;
        wT[(k + 2) * 129 + o] = v.z; wT[(k + 3) * 129 + o] = v.w;
    }
    __syncthreads();

    // L2: 64 -> 128
    {
        float a0 = bb2[lane], a1 = bb2[lane + 32], a2 = bb2[lane + 64], a3 = bb2[lane + 96];
#pragma unroll 4
        for (int k = 0; k < 64; k++) {
            float a = act[w][k];
            a0 = fmaf(a, wT[k * 129 + lane],      a0);
            a1 = fmaf(a, wT[k * 129 + lane + 32], a1);
            a2 = fmaf(a, wT[k * 129 + lane + 64], a2);
            a3 = fmaf(a, wT[k * 129 + lane + 96], a3);
        }
        a0 = fmaxf(a0, 0.0f); a1 = fmaxf(a1, 0.0f);
        a2 = fmaxf(a2, 0.0f); a3 = fmaxf(a3, 0.0f);
        __syncthreads();
        act[w][lane] = a0; act[w][lane + 32] = a1;
        act[w][lane + 64] = a2; act[w][lane + 96] = a3;
    }

    // ---- fc3 staging: [64][128] -> wT[k*65+o], 2048 float4 ----
#pragma unroll 2
    for (int idx4 = tid; idx4 < 2048; idx4 += 256) {
        float4 v = reinterpret_cast<const float4*>(fc3w)[idx4];
        int e = idx4 << 2;
        int o = e >> 7;
        int k = e & 127;
        wT[(k + 0) * 65 + o] = v.x; wT[(k + 1) * 65 + o] = v.y;
        wT[(k + 2) * 65 + o] = v.z; wT[(k + 3) * 65 + o] = v.w;
    }
    __syncthreads();

    // L3: 128 -> 64 (warp-private from here on)
    {
        float a0 = bb3[lane], a1 = bb3[lane + 32];
#pragma unroll 4
        for (int k = 0; k < 128; k++) {
            float a = act[w][k];
            a0 = fmaf(a, wT[k * 65 + lane], a0);
            a1 = fmaf(a, wT[k * 65 + lane + 32], a1);
        }
        a0 = fmaxf(a0, 0.0f); a1 = fmaxf(a1, 0.0f);
        __syncwarp();
        act[w][lane] = a0; act[w][lane + 32] = a1;
        __syncwarp();
    }

    // L4: 64 -> 4, sigmoid, gains (per warp)
    {
        int ol = lane & 3;
        float acc = b4s[ol];
#pragma unroll 4
        for (int k = 0; k < 64; k++)
            acc = fmaf(act[w][k], w4[k * 4 + ol], acc);
        float kv = 2.0f / (1.0f + expf(-acc)) - 1.0f;

        float k1 = __shfl_sync(0xffffffffu, kv, 0);
        float k2 = __shfl_sync(0xffffffffu, kv, 1);
        float k3 = __shfl_sync(0xffffffffu, kv, 2);
        float k4 = __shfl_sync(0xffffffffu, kv, 3);

        if (lane == 0) {
            float sg0 = sv.x - gv.x;
            float sg1 = sv.y - gv.y;
            out[r * 2 + 0] = -(k1 * sg0 + k2 * sv.z);
            out[r * 2 + 1] = -(k3 * sg1 + k4 * sv.w);
        }
    }
}

// ============================================================================
extern "C" void kernel_launch(void* const* d_in, const int* in_sizes, int n_in,
                              void* d_out, int out_size)
{
    const float* s    = (const float*)d_in[0];
    const float* g    = (const float*)d_in[1];
    const float* c1w  = (const float*)d_in[2];
    const float* c1b  = (const float*)d_in[3];
    const float* c2w  = (const float*)d_in[4];
    const float* c2b  = (const float*)d_in[5];
    const float* f1w  = (const float*)d_in[6];
    const float* f1b  = (const float*)d_in[7];
    const float* f2w  = (const float*)d_in[8];
    const float* f2b  = (const float*)d_in[9];
    const float* f3w  = (const float*)d_in[10];
    const float* f3b  = (const float*)d_in[11];
    const float* f4w  = (const float*)d_in[12];
    const float* f4b  = (const float*)d_in[13];
    float* out = (float*)d_out;

    pool_kernel<<<NPTS, 256>>>(s, c1w, c1b, c2w, c2b);
    trunk_kernel<<<NPTS / 8, 256>>>(s, g, f1w, f1b, f2w, f2b, f3w, f3b,
                                    f4w, f4b, out);
}

// round 5
// speedup vs baseline: 1.9422x; 1.0719x over previous
#include <cuda_runtime.h>

#define NPTS 1024

// ---------------- packed f32x2 helpers (Blackwell) ----------------
static __device__ __forceinline__ unsigned long long pack2(float lo, float hi) {
    unsigned long long r;
    asm("mov.b64 %0, {%1,%2};" : "=l"(r) : "f"(lo), "f"(hi));
    return r;
}
static __device__ __forceinline__ float2 unpack2(unsigned long long v) {
    float2 r;
    asm("mov.b64 {%0,%1}, %2;" : "=f"(r.x), "=f"(r.y) : "l"(v));
    return r;
}
static __device__ __forceinline__ void fma2(unsigned long long& d,
                                            unsigned long long a,
                                            unsigned long long b) {
    asm("fma.rn.f32x2 %0, %1, %2, %0;" : "+l"(d) : "l"(a), "l"(b));
}

// pooled[i][o] intermediate (device-global scratch; no allocations allowed)
__device__ float g_pooled[NPTS * 128];

// ============================================================================
// Kernel A: sparse per-pair MLP (5 -> 64 -> 128) + masked max-pool.
// Thread = (chpair p, k-half, nn-set): owns channels {p, p+64}, 32 k's, 4 of
// 8 neighbors. 2 channels per thread -> 4 fma2 per LDS.128 (2x the R4 ratio).
// smem ~27.5KB -> 8 blocks/SM (full occupancy).
// ============================================================================
__global__ __launch_bounds__(256, 2) void pool_kernel(
    const float* __restrict__ s,
    const float* __restrict__ w1g, const float* __restrict__ b1g,
    const float* __restrict__ w2g, const float* __restrict__ b2g)
{
    __shared__ __align__(16) float4 s4[NPTS];        // 16KB
    __shared__ int   nbr[NPTS];                      // 4KB
    __shared__ __align__(16) float h1[8 * 64];       // 2KB
    __shared__ float part[8][128];                   // 4KB
    __shared__ float w1s[64 * 5];
    __shared__ float b1s[64];
    __shared__ int cnt, cntp;

    const int tid   = threadIdx.x;
    const int p     = tid & 63;         // channel pair: ch {p, p+64}
    const int half  = (tid >> 6) & 1;   // k-half
    const int nnset = tid >> 7;         // neighbor set: nn in [nnset*4, +4)

    // ---- conv2 weights for 2 channels x 32 k's: 16 LDG.128, 32 f32x2 packs ----
    unsigned long long w2p[2][16];
    float b2r[2];
#pragma unroll
    for (int c = 0; c < 2; c++) {
        int ch = p + 64 * c;
        const float4* wr = reinterpret_cast<const float4*>(w2g + ch * 64 + half * 32);
        float4 wv[8];
#pragma unroll
        for (int q = 0; q < 8; q++) wv[q] = wr[q];
#pragma unroll
        for (int q = 0; q < 8; q++) {
            w2p[c][2 * q]     = pack2(wv[q].x, wv[q].y);
            w2p[c][2 * q + 1] = pack2(wv[q].z, wv[q].w);
        }
        b2r[c] = b2g[ch];
    }

    // ---- stage s (4 batched LDG.128 each), w1, b1 ----
#pragma unroll
    for (int j = 0; j < 4; j++)
        s4[tid + 256 * j] = reinterpret_cast<const float4*>(s)[tid + 256 * j];
    for (int idx = tid; idx < 320; idx += 256) w1s[idx] = w1g[idx];
    if (tid < 64) b1s[tid] = b1g[tid];
    if (tid == 0) cnt = 0;
    __syncthreads();

    const int   c1  = tid & 63;   // conv1 channel this thread computes
    const int   slb = tid >> 6;   // base slot 0..3 (handles slb and slb+4)
    const float w1r0 = w1s[c1 * 5 + 0], w1r1 = w1s[c1 * 5 + 1],
                w1r2 = w1s[c1 * 5 + 2], w1r3 = w1s[c1 * 5 + 3],
                w1r4 = w1s[c1 * 5 + 4], b1r = b1s[c1];

    const int i = blockIdx.x;
    const float4 si = s4[i];

    // ---- neighbor scan: dx^2+dy^2 < 0.25 (== dist < 0.5; self passes) ----
    for (int j = tid; j < NPTS; j += 256) {
        float4 sj = s4[j];
        float dx = si.x - sj.x, dy = si.y - sj.y;
        if (dx * dx + dy * dy < 0.25f) {
            int pq = atomicAdd(&cnt, 1);
            nbr[pq] = j;
        }
    }
    __syncthreads();
    if (tid == 0) {
        int c = cnt, cp = (c + 7) & ~7;
        for (int t = c; t < cp; t++) nbr[t] = i;  // pad with self (idempotent under max)
        cntp = cp;
    }
    __syncthreads();
    const int cp = cntp;

    float pooled[2] = {0.0f, 0.0f};  // max vs 0 covers mask zeros & relu

    for (int n = 0; n < cp; n += 8) {
        // conv1: thread computes h1[c1] for slots slb and slb+4
#pragma unroll
        for (int t = 0; t < 2; t++) {
            int sl = slb + 4 * t;
            int j  = nbr[n + sl];
            float4 sj = s4[j];
            float dx = si.x - sj.x, dy = si.y - sj.y;
            float dz = si.z - sj.z, dw = si.w - sj.w;
            float ind = (j == i) ? 1.0f : 0.0f;
            float v = b1r;
            v = fmaf(dx, w1r0, v);
            v = fmaf(dy, w1r1, v);
            v = fmaf(dz, w1r2, v);
            v = fmaf(dw, w1r3, v);
            v = fmaf(ind, w1r4, v);
            h1[sl * 64 + c1] = fmaxf(v, 0.0f);   // lane-consecutive: conflict-free
        }
        __syncthreads();

        // conv2: 4 neighbors x 2 channels x 32 k's; 1 LDS.128 feeds 4 fma2
        unsigned long long acc[2][4];
#pragma unroll
        for (int t = 0; t < 4; t++) { acc[0][t] = 0ull; acc[1][t] = 0ull; }

#pragma unroll
        for (int t = 0; t < 4; t++) {
            const ulonglong2* hb = reinterpret_cast<const ulonglong2*>(
                h1 + (nnset * 4 + t) * 64 + half * 32);
#pragma unroll
            for (int q = 0; q < 8; q++) {
                ulonglong2 hp = hb[q];            // LDS.128 broadcast
                fma2(acc[0][t], hp.x, w2p[0][2 * q]);
                fma2(acc[0][t], hp.y, w2p[0][2 * q + 1]);
                fma2(acc[1][t], hp.x, w2p[1][2 * q]);
                fma2(acc[1][t], hp.y, w2p[1][2 * q + 1]);
            }
        }

        // half 1 publishes its partial sums; half 0 keeps its own in registers
        if (half == 1) {
#pragma unroll
            for (int t = 0; t < 4; t++) {
                int nn = nnset * 4 + t;
                float2 f0 = unpack2(acc[0][t]);
                float2 f1 = unpack2(acc[1][t]);
                part[nn][p]      = f0.x + f0.y;
                part[nn][p + 64] = f1.x + f1.y;
            }
        }
        __syncthreads();
        if (half == 0) {
#pragma unroll
            for (int t = 0; t < 4; t++) {
                int nn = nnset * 4 + t;
                float2 f0 = unpack2(acc[0][t]);
                float2 f1 = unpack2(acc[1][t]);
                pooled[0] = fmaxf(pooled[0], f0.x + f0.y + part[nn][p]      + b2r[0]);
                pooled[1] = fmaxf(pooled[1], f1.x + f1.y + part[nn][p + 64] + b2r[1]);
            }
        }
        // hazards: h1 reads done before the barrier above; half1's next part
        // writes happen after the next post-conv1 barrier, which half0 only
        // reaches after finishing these part reads.
    }

    // cross-nnset combine through part scratch
    __syncthreads();
    if (half == 0 && nnset == 1) {
        part[0][p] = pooled[0];
        part[1][p] = pooled[1];
    }
    __syncthreads();
    if (half == 0 && nnset == 0) {
        g_pooled[i * 128 + p]      = fmaxf(pooled[0], part[0][p]);
        g_pooled[i * 128 + p + 64] = fmaxf(pooled[1], part[1][p]);
    }
}

// ============================================================================
// Kernel B: trunk  feat[132] -> 64 -> 128 -> 64 -> 4 -> (a_x, a_y)
// 128 blocks x 256 threads (8 warps), 1 row per warp.
// Weights staged as k-pair u64 (transposed, odd u64 pitch); GEMV via f32x2
// (1 act LDS.64 + 2 w LDS.64 + 2 fma2 per 4 MACs). Next layer's LDGs are
// issued before the current layer's compute to hide L2 latency.
// ============================================================================
__global__ __launch_bounds__(256) void trunk_kernel(
    const float* __restrict__ s, const float* __restrict__ g,
    const float* __restrict__ fc1w, const float* __restrict__ fc1b,
    const float* __restrict__ fc2w, const float* __restrict__ fc2b,
    const float* __restrict__ fc3w, const float* __restrict__ fc3b,
    const float* __restrict__ fc4w, const float* __restrict__ fc4b,
    float* __restrict__ out)
{
    __shared__ unsigned long long wP[66 * 65];   // 34.3KB, reused per layer
    __shared__ float w4[64 * 4];
    __shared__ float bb1[64], bb2[128], bb3[64], b4s[4];
    __shared__ __align__(16) float act[8][132];

    const int tid  = threadIdx.x;
    const int lane = tid & 31;
    const int w    = tid >> 5;
    const int r    = blockIdx.x * 8 + w;

    const float4 sv = reinterpret_cast<const float4*>(s)[r];
    const float2 gv = reinterpret_cast<const float2*>(g)[r];

    // ---- fc1 staging loads: 2112 float4, register-buffered (MLP 8-9) ----
    const float4* f1w4 = reinterpret_cast<const float4*>(fc1w);
    float4 v1[8];
#pragma unroll
    for (int rr = 0; rr < 8; rr++) v1[rr] = f1w4[tid + 256 * rr];
    float4 v1x;
    if (tid < 64) v1x = f1w4[2048 + tid];

    // feat = [pooled(128), s0-g0, s1-g1, s2, s3]
#pragma unroll
    for (int j = 0; j < 4; j++)
        act[w][lane + 32 * j] = g_pooled[r * 128 + lane + 32 * j];
    if (lane == 0) {
        act[w][128] = sv.x - gv.x;
        act[w][129] = sv.y - gv.y;
        act[w][130] = sv.z;
        act[w][131] = sv.w;
    }

    // biases + fc4
    if (tid < 64)  bb1[tid] = fc1b[tid];
    if (tid < 128) bb2[tid] = fc2b[tid];
    if (tid >= 128 && tid < 192) bb3[tid - 128] = fc3b[tid - 128];
    if (tid < 4)   b4s[tid] = fc4b[tid];
    if (tid < 64) {                       // fc4: 64 float4s
        float4 v = reinterpret_cast<const float4*>(fc4w)[tid];
        int o = tid >> 4;
        int k = (tid << 2) & 63;
        w4[(k + 0) * 4 + o] = v.x; w4[(k + 1) * 4 + o] = v.y;
        w4[(k + 2) * 4 + o] = v.z; w4[(k + 3) * 4 + o] = v.w;
    }

    // ---- STS fc1 as k-pair u64: wP[k2*65 + o] = (w[o][2k2], w[o][2k2+1]) ----
#pragma unroll
    for (int rr = 0; rr < 8; rr++) {
        int e = (tid + 256 * rr) << 2;
        int o = e / 132;                  // 132 % 4 == 0: no row straddle
        int k = e - o * 132;
        int k2 = k >> 1;
        wP[(k2 + 0) * 65 + o] = pack2(v1[rr].x, v1[rr].y);
        wP[(k2 + 1) * 65 + o] = pack2(v1[rr].z, v1[rr].w);
    }
    if (tid < 64) {
        int e = (2048 + tid) << 2;
        int o = e / 132;
        int k = e - o * 132;
        int k2 = k >> 1;
        wP[(k2 + 0) * 65 + o] = pack2(v1x.x, v1x.y);
        wP[(k2 + 1) * 65 + o] = pack2(v1x.z, v1x.w);
    }
    __syncthreads();

    // prefetch fc2 (2048 float4) before L1 compute
    const float4* f2w4 = reinterpret_cast<const float4*>(fc2w);
    float4 v2[8];
#pragma unroll
    for (int rr = 0; rr < 8; rr++) v2[rr] = f2w4[tid + 256 * rr];

    // L1: 132 -> 64 via f32x2 pairs
    {
        const unsigned long long* actp =
            reinterpret_cast<const unsigned long long*>(act[w]);
        unsigned long long a0p = 0ull, a1p = 0ull;
#pragma unroll 6
        for (int k2 = 0; k2 < 66; k2++) {
            unsigned long long ap = actp[k2];
            fma2(a0p, ap, wP[k2 * 65 + lane]);
            fma2(a1p, ap, wP[k2 * 65 + lane + 32]);
        }
        float2 f0 = unpack2(a0p), f1 = unpack2(a1p);
        float a0 = fmaxf(f0.x + f0.y + bb1[lane], 0.0f);
        float a1 = fmaxf(f1.x + f1.y + bb1[lane + 32], 0.0f);
        __syncthreads();                  // everyone done with fc1 weights
        act[w][lane] = a0; act[w][lane + 32] = a1;
    }

    // ---- STS fc2: [128][64] -> wP[k2*129 + o] ----
#pragma unroll
    for (int rr = 0; rr < 8; rr++) {
        int e = (tid + 256 * rr) << 2;
        int o = e >> 6;
        int k = e & 63;
        int k2 = k >> 1;
        wP[(k2 + 0) * 129 + o] = pack2(v2[rr].x, v2[rr].y);
        wP[(k2 + 1) * 129 + o] = pack2(v2[rr].z, v2[rr].w);
    }
    __syncthreads();

    // prefetch fc3 before L2 compute
    const float4* f3w4 = reinterpret_cast<const float4*>(fc3w);
    float4 v3[8];
#pragma unroll
    for (int rr = 0; rr < 8; rr++) v3[rr] = f3w4[tid + 256 * rr];

    // L2: 64 -> 128
    {
        const unsigned long long* actp =
            reinterpret_cast<const unsigned long long*>(act[w]);
        unsigned long long ac[4] = {0ull, 0ull, 0ull, 0ull};
#pragma unroll 4
        for (int k2 = 0; k2 < 32; k2++) {
            unsigned long long ap = actp[k2];
            fma2(ac[0], ap, wP[k2 * 129 + lane]);
            fma2(ac[1], ap, wP[k2 * 129 + lane + 32]);
            fma2(ac[2], ap, wP[k2 * 129 + lane + 64]);
            fma2(ac[3], ap, wP[k2 * 129 + lane + 96]);
        }
        float o0, o1, o2, o3;
        { float2 f = unpack2(ac[0]); o0 = fmaxf(f.x + f.y + bb2[lane],      0.0f); }
        { float2 f = unpack2(ac[1]); o1 = fmaxf(f.x + f.y + bb2[lane + 32], 0.0f); }
        { float2 f = unpack2(ac[2]); o2 = fmaxf(f.x + f.y + bb2[lane + 64], 0.0f); }
        { float2 f = unpack2(ac[3]); o3 = fmaxf(f.x + f.y + bb2[lane + 96], 0.0f); }
        __syncthreads();
        act[w][lane] = o0; act[w][lane + 32] = o1;
        act[w][lane + 64] = o2; act[w][lane + 96] = o3;
    }

    // ---- STS fc3: [64][128] -> wP[k2*65 + o] ----
#pragma unroll
    for (int rr = 0; rr < 8; rr++) {
        int e = (tid + 256 * rr) << 2;
        int o = e >> 7;
        int k = e & 127;
        int k2 = k >> 1;
        wP[(k2 + 0) * 65 + o] = pack2(v3[rr].x, v3[rr].y);
        wP[(k2 + 1) * 65 + o] = pack2(v3[rr].z, v3[rr].w);
    }
    __syncthreads();

    // L3: 128 -> 64 (warp-private from here on)
    {
        const unsigned long long* actp =
            reinterpret_cast<const unsigned long long*>(act[w]);
        unsigned long long a0p = 0ull, a1p = 0ull;
#pragma unroll 8
        for (int k2 = 0; k2 < 64; k2++) {
            unsigned long long ap = actp[k2];
            fma2(a0p, ap, wP[k2 * 65 + lane]);
            fma2(a1p, ap, wP[k2 * 65 + lane + 32]);
        }
        float2 f0 = unpack2(a0p), f1 = unpack2(a1p);
        float a0 = fmaxf(f0.x + f0.y + bb3[lane], 0.0f);
        float a1 = fmaxf(f1.x + f1.y + bb3[lane + 32], 0.0f);
        __syncwarp();
        act[w][lane] = a0; act[w][lane + 32] = a1;
        __syncwarp();
    }

    // L4: 64 -> 4, sigmoid, gains (per warp)
    {
        int ol = lane & 3;
        float acc = b4s[ol];
#pragma unroll 4
        for (int k = 0; k < 64; k++)
            acc = fmaf(act[w][k], w4[k * 4 + ol], acc);
        float kv = 2.0f / (1.0f + expf(-acc)) - 1.0f;

        float k1 = __shfl_sync(0xffffffffu, kv, 0);
        float k2 = __shfl_sync(0xffffffffu, kv, 1);
        float k3 = __shfl_sync(0xffffffffu, kv, 2);
        float k4 = __shfl_sync(0xffffffffu, kv, 3);

        if (lane == 0) {
            float sg0 = sv.x - gv.x;
            float sg1 = sv.y - gv.y;
            out[r * 2 + 0] = -(k1 * sg0 + k2 * sv.z);
            out[r * 2 + 1] = -(k3 * sg1 + k4 * sv.w);
        }
    }
}

// ============================================================================
extern "C" void kernel_launch(void* const* d_in, const int* in_sizes, int n_in,
                              void* d_out, int out_size)
{
    const float* s    = (const float*)d_in[0];
    const float* g    = (const float*)d_in[1];
    const float* c1w  = (const float*)d_in[2];
    const float* c1b  = (const float*)d_in[3];
    const float* c2w  = (const float*)d_in[4];
    const float* c2b  = (const float*)d_in[5];
    const float* f1w  = (const float*)d_in[6];
    const float* f1b  = (const float*)d_in[7];
    const float* f2w  = (const float*)d_in[8];
    const float* f2b  = (const float*)d_in[9];
    const float* f3w  = (const float*)d_in[10];
    const float* f3b  = (const float*)d_in[11];
    const float* f4w  = (const float*)d_in[12];
    const float* f4b  = (const float*)d_in[13];
    float* out = (float*)d_out;

    pool_kernel<<<NPTS, 256>>>(s, c1w, c1b, c2w, c2b);
    trunk_kernel<<<NPTS / 8, 256>>>(s, g, f1w, f1b, f2w, f2b, f3w, f3b,
                                    f4w, f4b, out);
}